// round 2
// baseline (speedup 1.0000x reference)
#include <cuda_runtime.h>

#define NN   100000
#define FIN  512
#define H1   8
#define D1   64      // H1*C1
#define C2   10

// ---------------- scratch (no allocs allowed) ----------------
#define EMAXSZ 1700000   // capacity: E + N self loops
__device__ float g_h1 [NN * D1];              // layer1 features       25.6 MB
__device__ float g_al1[NN * H1];              // src attention terms
__device__ float g_ar1[NN * H1];              // dst attention terms
__device__ float g_d1 [NN * H1];              // softmax denom -> reciprocal
__device__ float g_ex1[(size_t)EMAXSZ * H1];  // per-edge exp          54.4 MB
__device__ float g_out1[NN * D1];             // layer1 aggregate      25.6 MB
__device__ float g_z2 [NN * C2];              // layer2 transformed feats
__device__ float g_al2[NN];
__device__ float g_ar2[NN];
__device__ float g_d2 [NN];
__device__ float g_ex2[EMAXSZ];
__device__ float g_out2[NN * C2];

// ---------------- helpers ----------------
__device__ __forceinline__ float lrelu(float x) { return x > 0.f ? x : 0.2f * x; }

// exp(x) via degree-6 polynomial on 2^f, FMA-pipe only (no MUFU). rel err ~8e-6.
__device__ __forceinline__ float fast_exp(float x) {
    float t = x * 1.4426950408889634f;
    t = fminf(fmaxf(t, -126.f), 126.f);
    float fi = floorf(t);
    float f  = t - fi;
    int   i  = (int)fi;
    float p = 1.5403530e-4f;
    p = fmaf(p, f, 1.3333558e-3f);
    p = fmaf(p, f, 9.6181291e-3f);
    p = fmaf(p, f, 5.5504109e-2f);
    p = fmaf(p, f, 2.4022651e-1f);
    p = fmaf(p, f, 6.9314718e-1f);
    p = fmaf(p, f, 1.0f);
    return __uint_as_float(__float_as_uint(p) + ((unsigned)i << 23));
}

__device__ __forceinline__ float elu1(float x) {
    return x > 0.f ? x : fast_exp(fmaxf(x, -80.f)) - 1.f;
}

// ---------------- kernels ----------------
__global__ void init_kernel() {
    int i = blockIdx.x * blockDim.x + threadIdx.x;
    if (i < NN * D1) g_out1[i] = 0.f;
    if (i < NN * H1) g_d1[i]   = 0.f;
    if (i < NN * C2) g_out2[i] = 0.f;
    if (i < NN)      g_d2[i]   = 0.f;
}

// h1 = x @ W1   (100000x512 @ 512x64), 64x64 block tile, 4x4 microtile
__global__ void gemm1_kernel(const float* __restrict__ x, const float* __restrict__ W) {
    __shared__ float As[32][64];   // [k][m]
    __shared__ float Bs[32][64];   // [k][n]
    int t  = threadIdx.x;          // 256
    int m0 = blockIdx.x * 64;
    int tx = (t & 15) * 4;
    int ty = (t >> 4) * 4;
    int lm = t & 63;
    int lk = (t >> 6) * 4;         // 0,4,8,12
    int kr = t >> 4;               // 0..15
    int nc = (t & 15) * 4;

    float acc[4][4];
#pragma unroll
    for (int i = 0; i < 4; i++)
#pragma unroll
        for (int j = 0; j < 4; j++) acc[i][j] = 0.f;

    int  row = m0 + lm;
    bool rok = row < NN;
    const float4* xrow = (const float4*)(x + (size_t)(rok ? row : 0) * FIN);

    for (int k0 = 0; k0 < FIN; k0 += 32) {
#pragma unroll
        for (int rep = 0; rep < 2; rep++) {
            int kk = lk + rep * 16;
            float4 v = rok ? xrow[(k0 + kk) >> 2] : make_float4(0.f, 0.f, 0.f, 0.f);
            As[kk + 0][lm] = v.x;
            As[kk + 1][lm] = v.y;
            As[kk + 2][lm] = v.z;
            As[kk + 3][lm] = v.w;
        }
#pragma unroll
        for (int rep = 0; rep < 2; rep++) {
            float4 v = *(const float4*)(W + (size_t)(k0 + kr + rep * 16) * D1 + nc);
            *(float4*)&Bs[kr + rep * 16][nc] = v;
        }
        __syncthreads();
#pragma unroll
        for (int kk = 0; kk < 32; kk++) {
            float4 a = *(const float4*)&As[kk][ty];
            float4 b = *(const float4*)&Bs[kk][tx];
            acc[0][0] = fmaf(a.x, b.x, acc[0][0]); acc[0][1] = fmaf(a.x, b.y, acc[0][1]);
            acc[0][2] = fmaf(a.x, b.z, acc[0][2]); acc[0][3] = fmaf(a.x, b.w, acc[0][3]);
            acc[1][0] = fmaf(a.y, b.x, acc[1][0]); acc[1][1] = fmaf(a.y, b.y, acc[1][1]);
            acc[1][2] = fmaf(a.y, b.z, acc[1][2]); acc[1][3] = fmaf(a.y, b.w, acc[1][3]);
            acc[2][0] = fmaf(a.z, b.x, acc[2][0]); acc[2][1] = fmaf(a.z, b.y, acc[2][1]);
            acc[2][2] = fmaf(a.z, b.z, acc[2][2]); acc[2][3] = fmaf(a.z, b.w, acc[2][3]);
            acc[3][0] = fmaf(a.w, b.x, acc[3][0]); acc[3][1] = fmaf(a.w, b.y, acc[3][1]);
            acc[3][2] = fmaf(a.w, b.z, acc[3][2]); acc[3][3] = fmaf(a.w, b.w, acc[3][3]);
        }
        __syncthreads();
    }
#pragma unroll
    for (int i = 0; i < 4; i++) {
        int r = m0 + ty + i;
        if (r < NN)
            *(float4*)&g_h1[(size_t)r * D1 + tx] =
                make_float4(acc[i][0], acc[i][1], acc[i][2], acc[i][3]);
    }
}

// per-node attention terms: al1[n,h] = sum_c h1[n,h,c]*a_src[h,c]
__global__ void attn1_kernel(const float* __restrict__ a_src, const float* __restrict__ a_dst) {
    int warp = (blockIdx.x * blockDim.x + threadIdx.x) >> 5;
    int lane = threadIdx.x & 31;
    if (warp >= NN) return;
    const float* hrow = g_h1 + (size_t)warp * D1;
    float v0 = hrow[lane], v1 = hrow[lane + 32];
    float s0 = v0 * __ldg(&a_src[lane]),  s1 = v1 * __ldg(&a_src[lane + 32]);
    float d0 = v0 * __ldg(&a_dst[lane]),  d1 = v1 * __ldg(&a_dst[lane + 32]);
#pragma unroll
    for (int off = 4; off; off >>= 1) {
        s0 += __shfl_xor_sync(~0u, s0, off);
        s1 += __shfl_xor_sync(~0u, s1, off);
        d0 += __shfl_xor_sync(~0u, d0, off);
        d1 += __shfl_xor_sync(~0u, d1, off);
    }
    if ((lane & 7) == 0) {
        int h = lane >> 3;
        g_al1[warp * H1 + h]     = s0;
        g_al1[warp * H1 + h + 4] = s1;
        g_ar1[warp * H1 + h]     = d0;
        g_ar1[warp * H1 + h + 4] = d1;
    }
}

// edge_index is int32 (JAX x64 disabled downcasts int64 -> int32)
__device__ __forceinline__ bool edge_sd(const int* __restrict__ src,
                                        const int* __restrict__ dst,
                                        int e, int E, int& s, int& d) {
    if (e < E) { s = src[e]; d = dst[e]; }
    else       { s = d = e - E; }
    return (unsigned)s < NN && (unsigned)d < NN;
}

// layer-1 edge pass A: ex1 = exp(lrelu(al[src]+ar[dst])), accumulate denom
__global__ void edgeA1_kernel(const int* __restrict__ src,
                              const int* __restrict__ dst, int E) {
    int e = blockIdx.x * blockDim.x + threadIdx.x;
    if (e >= E + NN) return;
    int s, d;
    if (!edge_sd(src, dst, e, E, s, d)) return;
    float4 a0 = *(const float4*)&g_al1[s * H1];
    float4 a1 = *(const float4*)&g_al1[s * H1 + 4];
    float4 r0 = *(const float4*)&g_ar1[d * H1];
    float4 r1 = *(const float4*)&g_ar1[d * H1 + 4];
    float4 e0 = make_float4(fast_exp(lrelu(a0.x + r0.x)), fast_exp(lrelu(a0.y + r0.y)),
                            fast_exp(lrelu(a0.z + r0.z)), fast_exp(lrelu(a0.w + r0.w)));
    float4 e1 = make_float4(fast_exp(lrelu(a1.x + r1.x)), fast_exp(lrelu(a1.y + r1.y)),
                            fast_exp(lrelu(a1.z + r1.z)), fast_exp(lrelu(a1.w + r1.w)));
    *(float4*)&g_ex1[(size_t)e * H1]     = e0;
    *(float4*)&g_ex1[(size_t)e * H1 + 4] = e1;
    atomicAdd((float4*)&g_d1[d * H1],     e0);
    atomicAdd((float4*)&g_d1[d * H1 + 4], e1);
}

__global__ void invd1_kernel() {
    int i = blockIdx.x * blockDim.x + threadIdx.x;
    if (i < NN * H1) g_d1[i] = 1.f / (g_d1[i] + 1e-16f);
}

// layer-1 edge pass B: out1[dst] += h1[src] * alpha
__global__ void edgeB1_kernel(const int* __restrict__ src,
                              const int* __restrict__ dst, int E) {
    int e = blockIdx.x * blockDim.x + threadIdx.x;
    if (e >= E + NN) return;
    int s, d;
    if (!edge_sd(src, dst, e, E, s, d)) return;
    float4 x0 = *(const float4*)&g_ex1[(size_t)e * H1];
    float4 x1 = *(const float4*)&g_ex1[(size_t)e * H1 + 4];
    float4 r0 = *(const float4*)&g_d1[d * H1];
    float4 r1 = *(const float4*)&g_d1[d * H1 + 4];
    float alpha[8] = { x0.x * r0.x, x0.y * r0.y, x0.z * r0.z, x0.w * r0.w,
                       x1.x * r1.x, x1.y * r1.y, x1.z * r1.z, x1.w * r1.w };
    const float* hs = g_h1  + (size_t)s * D1;
    float*       od = g_out1 + (size_t)d * D1;
#pragma unroll
    for (int h = 0; h < 8; h++) {
        float a = alpha[h];
        float4 v0 = *(const float4*)&hs[h * 8];
        float4 v1 = *(const float4*)&hs[h * 8 + 4];
        atomicAdd((float4*)&od[h * 8],
                  make_float4(v0.x * a, v0.y * a, v0.z * a, v0.w * a));
        atomicAdd((float4*)&od[h * 8 + 4],
                  make_float4(v1.x * a, v1.y * a, v1.z * a, v1.w * a));
    }
}

// layer-2 node prep: h2 = elu(out1+b1); z2 = h2@W2; al2/ar2 attention terms
__global__ void node2_kernel(const float* __restrict__ b1, const float* __restrict__ W2,
                             const float* __restrict__ as2, const float* __restrict__ ad2) {
    int warp = (blockIdx.x * blockDim.x + threadIdx.x) >> 5;
    int lane = threadIdx.x & 31;
    if (warp >= NN) return;
    const float* orow = g_out1 + (size_t)warp * D1;
    float o0 = elu1(orow[lane]      + __ldg(&b1[lane]));
    float o1 = elu1(orow[lane + 32] + __ldg(&b1[lane + 32]));
    float p[C2];
#pragma unroll
    for (int c = 0; c < C2; c++)
        p[c] = fmaf(o0, __ldg(&W2[lane * C2 + c]),
               o1 * __ldg(&W2[(lane + 32) * C2 + c]));
#pragma unroll
    for (int off = 16; off; off >>= 1)
#pragma unroll
        for (int c = 0; c < C2; c++) p[c] += __shfl_xor_sync(~0u, p[c], off);
    float al = 0.f, ar = 0.f;
#pragma unroll
    for (int c = 0; c < C2; c++) {
        al = fmaf(p[c], __ldg(&as2[c]), al);
        ar = fmaf(p[c], __ldg(&ad2[c]), ar);
    }
    if (lane < C2) g_z2[warp * C2 + lane] = p[lane];
    if (lane == 0) { g_al2[warp] = al; g_ar2[warp] = ar; }
}

__global__ void edgeA2_kernel(const int* __restrict__ src,
                              const int* __restrict__ dst, int E) {
    int e = blockIdx.x * blockDim.x + threadIdx.x;
    if (e >= E + NN) return;
    int s, d;
    if (!edge_sd(src, dst, e, E, s, d)) return;
    float ex = fast_exp(lrelu(g_al2[s] + g_ar2[d]));
    g_ex2[e] = ex;
    atomicAdd(&g_d2[d], ex);
}

__global__ void invd2_kernel() {
    int i = blockIdx.x * blockDim.x + threadIdx.x;
    if (i < NN) g_d2[i] = 1.f / (g_d2[i] + 1e-16f);
}

__global__ void edgeB2_kernel(const int* __restrict__ src,
                              const int* __restrict__ dst, int E) {
    int e = blockIdx.x * blockDim.x + threadIdx.x;
    if (e >= E + NN) return;
    int s, d;
    if (!edge_sd(src, dst, e, E, s, d)) return;
    float a = g_ex2[e] * g_d2[d];
    const float2* zs = (const float2*)(g_z2  + (size_t)s * C2);
    float2*       od = (float2*)(g_out2 + (size_t)d * C2);
#pragma unroll
    for (int i = 0; i < 5; i++) {
        float2 v = zs[i];
        atomicAdd(&od[i], make_float2(v.x * a, v.y * a));
    }
}

__global__ void final_kernel(const float* __restrict__ b2, float* __restrict__ out) {
    int n = blockIdx.x * blockDim.x + threadIdx.x;
    if (n >= NN) return;
    float v[C2];
    float m = -1e30f;
#pragma unroll
    for (int c = 0; c < C2; c++) {
        v[c] = g_out2[(size_t)n * C2 + c] + __ldg(&b2[c]);
        m = fmaxf(m, v[c]);
    }
    float s = 0.f;
#pragma unroll
    for (int c = 0; c < C2; c++) s += fast_exp(v[c] - m);
    float l = m + logf(s);
#pragma unroll
    for (int c = 0; c < C2; c++) out[(size_t)n * C2 + c] = v[c] - l;
}

// ---------------- launch ----------------
extern "C" void kernel_launch(void* const* d_in, const int* in_sizes, int n_in,
                              void* d_out, int out_size) {
    const float* x   = (const float*)d_in[0];
    const int*   ei  = (const int*)d_in[1];    // int32: JAX x64-disabled
    const float* W1  = (const float*)d_in[2];
    const float* as1 = (const float*)d_in[3];
    const float* ad1 = (const float*)d_in[4];
    const float* b1  = (const float*)d_in[5];
    const float* W2  = (const float*)d_in[6];
    const float* as2 = (const float*)d_in[7];
    const float* ad2 = (const float*)d_in[8];
    const float* b2  = (const float*)d_in[9];

    int E = in_sizes[1] / 2;
    const int* src = ei;
    const int* dst = ei + E;
    int tot = E + NN;

    init_kernel <<<(NN * D1 + 255) / 256, 256>>>();
    gemm1_kernel<<<(NN + 63) / 64, 256>>>(x, W1);
    attn1_kernel<<<(NN * 32 + 255) / 256, 256>>>(as1, ad1);
    edgeA1_kernel<<<(tot + 255) / 256, 256>>>(src, dst, E);
    invd1_kernel<<<(NN * H1 + 255) / 256, 256>>>();
    edgeB1_kernel<<<(tot + 255) / 256, 256>>>(src, dst, E);
    node2_kernel<<<(NN * 32 + 255) / 256, 256>>>(b1, W2, as2, ad2);
    edgeA2_kernel<<<(tot + 255) / 256, 256>>>(src, dst, E);
    invd2_kernel<<<(NN + 255) / 256, 256>>>();
    edgeB2_kernel<<<(tot + 255) / 256, 256>>>(src, dst, E);
    final_kernel<<<(NN + 255) / 256, 256>>>(b2, (float*)d_out);
}

// round 4
// speedup vs baseline: 1.0431x; 1.0431x over previous
#include <cuda_runtime.h>
#include <cstdint>

#define NN   100000
#define FIN  512
#define H1   8
#define D1   64      // H1*C1
#define C2   10

// ---------------- scratch (no allocs allowed) ----------------
__device__ float g_h1 [NN * D1];     // layer1 features   25.6 MB
__device__ float g_al1[NN * H1];
__device__ float g_ar1[NN * H1];
__device__ float g_d1 [NN * H1];     // softmax denominators
__device__ float g_out1[NN * D1];    // layer1 numerator  25.6 MB
__device__ float g_z2 [NN * C2];
__device__ float g_al2[NN];
__device__ float g_ar2[NN];
__device__ float g_d2 [NN];
__device__ float g_out2[NN * C2];

// ---------------- helpers ----------------
__device__ __forceinline__ float lrelu(float x) { return x > 0.f ? x : 0.2f * x; }

// exp via degree-6 polynomial, FMA-pipe only. rel err ~8e-6.
__device__ __forceinline__ float fast_exp(float x) {
    float t = x * 1.4426950408889634f;
    t = fminf(fmaxf(t, -126.f), 126.f);
    float fi = floorf(t);
    float f  = t - fi;
    int   i  = (int)fi;
    float p = 1.5403530e-4f;
    p = fmaf(p, f, 1.3333558e-3f);
    p = fmaf(p, f, 9.6181291e-3f);
    p = fmaf(p, f, 5.5504109e-2f);
    p = fmaf(p, f, 2.4022651e-1f);
    p = fmaf(p, f, 6.9314718e-1f);
    p = fmaf(p, f, 1.0f);
    return __uint_as_float(__float_as_uint(p) + ((unsigned)i << 23));
}

__device__ __forceinline__ float elu1(float x) {
    return x > 0.f ? x : fast_exp(fmaxf(x, -80.f)) - 1.f;
}

// packed fp32x2 (Blackwell base ISA; doubles fp32 FMA throughput)
__device__ __forceinline__ unsigned long long rep2(float v) {
    unsigned long long r;
    asm("mov.b64 %0, {%1, %1};" : "=l"(r) : "f"(v));
    return r;
}
__device__ __forceinline__ void ffma2(unsigned long long& d,
                                      unsigned long long a, unsigned long long b) {
    asm("fma.rn.f32x2 %0, %1, %2, %0;" : "+l"(d) : "l"(a), "l"(b));
}
__device__ __forceinline__ float2 unpk(unsigned long long v) {
    float lo, hi;
    asm("mov.b64 {%0, %1}, %2;" : "=f"(lo), "=f"(hi) : "l"(v));
    return make_float2(lo, hi);
}

// ---------------- kernels ----------------
__global__ void init_kernel() {
    int i = blockIdx.x * blockDim.x + threadIdx.x;
    if (i < NN * D1) g_out1[i] = 0.f;
    if (i < NN * H1) g_d1[i]   = 0.f;
    if (i < NN * C2) g_out2[i] = 0.f;
    if (i < NN)      g_d2[i]   = 0.f;
}

// h1 = x @ W1 (100000x512 @ 512x64), 64x64 tile, 4x4 microtile, packed f32x2 FMA
__global__ void gemm1_kernel(const float* __restrict__ x, const float* __restrict__ W) {
    __shared__ __align__(16) float As[32][64];   // [k][m]
    __shared__ __align__(16) float Bs[32][64];   // [k][n]
    int t  = threadIdx.x;          // 256
    int m0 = blockIdx.x * 64;
    int tx = (t & 15) * 4;
    int ty = (t >> 4) * 4;
    int lm = t & 63;
    int lk = (t >> 6) * 4;
    int kr = t >> 4;
    int nc = (t & 15) * 4;

    // acc[i][p]: row ty+i, n-pair p covering cols (tx+2p, tx+2p+1), packed f32x2
    unsigned long long acc[4][2];
#pragma unroll
    for (int i = 0; i < 4; i++) { acc[i][0] = 0ull; acc[i][1] = 0ull; }

    int  row = m0 + lm;
    bool rok = row < NN;
    const float4* xrow = (const float4*)(x + (size_t)(rok ? row : 0) * FIN);

    for (int k0 = 0; k0 < FIN; k0 += 32) {
#pragma unroll
        for (int rep = 0; rep < 2; rep++) {
            int kk = lk + rep * 16;
            float4 v = rok ? xrow[(k0 + kk) >> 2] : make_float4(0.f, 0.f, 0.f, 0.f);
            As[kk + 0][lm] = v.x;
            As[kk + 1][lm] = v.y;
            As[kk + 2][lm] = v.z;
            As[kk + 3][lm] = v.w;
        }
#pragma unroll
        for (int rep = 0; rep < 2; rep++) {
            float4 v = *(const float4*)(W + (size_t)(k0 + kr + rep * 16) * D1 + nc);
            *(float4*)&Bs[kr + rep * 16][nc] = v;
        }
        __syncthreads();
#pragma unroll
        for (int kk = 0; kk < 32; kk++) {
            float4 a = *(const float4*)&As[kk][ty];
            ulonglong2 bb = *(const ulonglong2*)&Bs[kk][tx];  // 2 packed n-pairs
            unsigned long long a0 = rep2(a.x), a1 = rep2(a.y),
                               a2 = rep2(a.z), a3 = rep2(a.w);
            ffma2(acc[0][0], a0, bb.x); ffma2(acc[0][1], a0, bb.y);
            ffma2(acc[1][0], a1, bb.x); ffma2(acc[1][1], a1, bb.y);
            ffma2(acc[2][0], a2, bb.x); ffma2(acc[2][1], a2, bb.y);
            ffma2(acc[3][0], a3, bb.x); ffma2(acc[3][1], a3, bb.y);
        }
        __syncthreads();
    }
#pragma unroll
    for (int i = 0; i < 4; i++) {
        int r = m0 + ty + i;
        if (r < NN) {
            float2 u0 = unpk(acc[i][0]), u1 = unpk(acc[i][1]);
            *(float4*)&g_h1[(size_t)r * D1 + tx] = make_float4(u0.x, u0.y, u1.x, u1.y);
        }
    }
}

// per-node attention terms
__global__ void attn1_kernel(const float* __restrict__ a_src, const float* __restrict__ a_dst) {
    int warp = (blockIdx.x * blockDim.x + threadIdx.x) >> 5;
    int lane = threadIdx.x & 31;
    if (warp >= NN) return;
    const float* hrow = g_h1 + (size_t)warp * D1;
    float v0 = hrow[lane], v1 = hrow[lane + 32];
    float s0 = v0 * __ldg(&a_src[lane]),  s1 = v1 * __ldg(&a_src[lane + 32]);
    float d0 = v0 * __ldg(&a_dst[lane]),  d1 = v1 * __ldg(&a_dst[lane + 32]);
#pragma unroll
    for (int off = 4; off; off >>= 1) {
        s0 += __shfl_xor_sync(~0u, s0, off);
        s1 += __shfl_xor_sync(~0u, s1, off);
        d0 += __shfl_xor_sync(~0u, d0, off);
        d1 += __shfl_xor_sync(~0u, d1, off);
    }
    if ((lane & 7) == 0) {
        int h = lane >> 3;
        g_al1[warp * H1 + h]     = s0;
        g_al1[warp * H1 + h + 4] = s1;
        g_ar1[warp * H1 + h]     = d0;
        g_ar1[warp * H1 + h + 4] = d1;
    }
}

// edge_index is int32 (JAX x64 disabled)
__device__ __forceinline__ bool edge_sd(const int* __restrict__ src,
                                        const int* __restrict__ dst,
                                        int e, int E, int& s, int& d) {
    if (e < E) { s = src[e]; d = dst[e]; }
    else       { s = d = e - E; }
    return (unsigned)s < NN && (unsigned)d < NN;
}

// ONE-PASS layer-1 edge kernel:
//   ex = exp(lrelu(al[s]+ar[d]));  d1[d] += ex;  out1[d] += h1[s]*ex
// normalization by (d1+eps) happens per-node in node2_kernel (exactly equal
// to alpha = ex/(denom+eps) summed per edge).
__global__ void edge1_kernel(const int* __restrict__ src,
                             const int* __restrict__ dst, int E) {
    int e = blockIdx.x * blockDim.x + threadIdx.x;
    if (e >= E + NN) return;
    int s, d;
    if (!edge_sd(src, dst, e, E, s, d)) return;
    float4 a0 = *(const float4*)&g_al1[s * H1];
    float4 a1 = *(const float4*)&g_al1[s * H1 + 4];
    float4 r0 = *(const float4*)&g_ar1[d * H1];
    float4 r1 = *(const float4*)&g_ar1[d * H1 + 4];
    float ex[8] = { fast_exp(lrelu(a0.x + r0.x)), fast_exp(lrelu(a0.y + r0.y)),
                    fast_exp(lrelu(a0.z + r0.z)), fast_exp(lrelu(a0.w + r0.w)),
                    fast_exp(lrelu(a1.x + r1.x)), fast_exp(lrelu(a1.y + r1.y)),
                    fast_exp(lrelu(a1.z + r1.z)), fast_exp(lrelu(a1.w + r1.w)) };
    atomicAdd((float4*)&g_d1[d * H1],     make_float4(ex[0], ex[1], ex[2], ex[3]));
    atomicAdd((float4*)&g_d1[d * H1 + 4], make_float4(ex[4], ex[5], ex[6], ex[7]));
    const float* hs = g_h1  + (size_t)s * D1;
    float*       od = g_out1 + (size_t)d * D1;
#pragma unroll
    for (int h = 0; h < 8; h++) {
        float a = ex[h];
        float4 v0 = *(const float4*)&hs[h * 8];
        float4 v1 = *(const float4*)&hs[h * 8 + 4];
        atomicAdd((float4*)&od[h * 8],
                  make_float4(v0.x * a, v0.y * a, v0.z * a, v0.w * a));
        atomicAdd((float4*)&od[h * 8 + 4],
                  make_float4(v1.x * a, v1.y * a, v1.z * a, v1.w * a));
    }
}

// layer-2 node prep: h2 = elu(out1/denom + b1); z2 = h2@W2; attention terms
__global__ void node2_kernel(const float* __restrict__ b1, const float* __restrict__ W2,
                             const float* __restrict__ as2, const float* __restrict__ ad2) {
    int warp = (blockIdx.x * blockDim.x + threadIdx.x) >> 5;
    int lane = threadIdx.x & 31;
    if (warp >= NN) return;
    const float* orow = g_out1 + (size_t)warp * D1;
    float rc0 = 1.f / (g_d1[warp * H1 + (lane >> 3)]     + 1e-16f);
    float rc1 = 1.f / (g_d1[warp * H1 + (lane >> 3) + 4] + 1e-16f);
    float o0 = elu1(fmaf(orow[lane],      rc0, __ldg(&b1[lane])));
    float o1 = elu1(fmaf(orow[lane + 32], rc1, __ldg(&b1[lane + 32])));
    float p[C2];
#pragma unroll
    for (int c = 0; c < C2; c++)
        p[c] = fmaf(o0, __ldg(&W2[lane * C2 + c]),
               o1 * __ldg(&W2[(lane + 32) * C2 + c]));
#pragma unroll
    for (int off = 16; off; off >>= 1)
#pragma unroll
        for (int c = 0; c < C2; c++) p[c] += __shfl_xor_sync(~0u, p[c], off);
    float al = 0.f, ar = 0.f;
#pragma unroll
    for (int c = 0; c < C2; c++) {
        al = fmaf(p[c], __ldg(&as2[c]), al);
        ar = fmaf(p[c], __ldg(&ad2[c]), ar);
    }
    if (lane < C2) g_z2[warp * C2 + lane] = p[lane];
    if (lane == 0) { g_al2[warp] = al; g_ar2[warp] = ar; }
}

// ONE-PASS layer-2 edge kernel
__global__ void edge2_kernel(const int* __restrict__ src,
                             const int* __restrict__ dst, int E) {
    int e = blockIdx.x * blockDim.x + threadIdx.x;
    if (e >= E + NN) return;
    int s, d;
    if (!edge_sd(src, dst, e, E, s, d)) return;
    float ex = fast_exp(lrelu(g_al2[s] + g_ar2[d]));
    atomicAdd(&g_d2[d], ex);
    const float2* zs = (const float2*)(g_z2  + (size_t)s * C2);
    float2*       od = (float2*)(g_out2 + (size_t)d * C2);
#pragma unroll
    for (int i = 0; i < 5; i++) {
        float2 v = zs[i];
        atomicAdd(&od[i], make_float2(v.x * ex, v.y * ex));
    }
}

__global__ void final_kernel(const float* __restrict__ b2, float* __restrict__ out) {
    int n = blockIdx.x * blockDim.x + threadIdx.x;
    if (n >= NN) return;
    float rc = 1.f / (g_d2[n] + 1e-16f);
    float v[C2];
    float m = -1e30f;
#pragma unroll
    for (int c = 0; c < C2; c++) {
        v[c] = fmaf(g_out2[(size_t)n * C2 + c], rc, __ldg(&b2[c]));
        m = fmaxf(m, v[c]);
    }
    float s = 0.f;
#pragma unroll
    for (int c = 0; c < C2; c++) s += fast_exp(v[c] - m);
    float l = m + logf(s);
#pragma unroll
    for (int c = 0; c < C2; c++) out[(size_t)n * C2 + c] = v[c] - l;
}

// ---------------- launch ----------------
extern "C" void kernel_launch(void* const* d_in, const int* in_sizes, int n_in,
                              void* d_out, int out_size) {
    const float* x   = (const float*)d_in[0];
    const int*   ei  = (const int*)d_in[1];    // int32 (JAX x64 disabled)
    const float* W1  = (const float*)d_in[2];
    const float* as1 = (const float*)d_in[3];
    const float* ad1 = (const float*)d_in[4];
    const float* b1  = (const float*)d_in[5];
    const float* W2  = (const float*)d_in[6];
    const float* as2 = (const float*)d_in[7];
    const float* ad2 = (const float*)d_in[8];
    const float* b2  = (const float*)d_in[9];

    int E = in_sizes[1] / 2;
    const int* src = ei;
    const int* dst = ei + E;
    int tot = E + NN;

    init_kernel <<<(NN * D1 + 255) / 256, 256>>>();
    gemm1_kernel<<<(NN + 63) / 64, 256>>>(x, W1);
    attn1_kernel<<<(NN * 32 + 255) / 256, 256>>>(as1, ad1);
    edge1_kernel<<<(tot + 255) / 256, 256>>>(src, dst, E);
    node2_kernel<<<(NN * 32 + 255) / 256, 256>>>(b1, W2, as2, ad2);
    edge2_kernel<<<(tot + 255) / 256, 256>>>(src, dst, E);
    final_kernel<<<(NN + 255) / 256, 256>>>(b2, (float*)d_out);
}

// round 5
// speedup vs baseline: 1.2641x; 1.2118x over previous
#include <cuda_runtime.h>
#include <cstdint>

#define NN   100000
#define FIN  512
#define H1   8
#define D1   64      // H1*C1
#define C2   10
#define EMAXSZ 1700000

// ---------------- scratch (no allocs allowed) ----------------
__device__ float g_h1 [NN * D1];     // layer1 features   25.6 MB
__device__ float g_al1[NN * H1];
__device__ float g_ar1[NN * H1];
__device__ float g_d1 [NN * H1];     // softmax denominators
__device__ float g_out1[NN * D1];    // layer1 numerator  25.6 MB
__device__ float g_z2 [NN * C2];
__device__ float g_al2[NN];
__device__ float g_ar2[NN];
// sorted-by-dst edge structures
__device__ int   g_cnt [NN];
__device__ int   g_tmp [NN];
__device__ int   g_bsum[128];
__device__ int   g_bsum2[128];
__device__ int   g_off [NN + 1];
__device__ int   g_pos [NN];
__device__ int   g_esrc[EMAXSZ];

// ---------------- helpers ----------------
__device__ __forceinline__ float lrelu(float x) { return x > 0.f ? x : 0.2f * x; }

__device__ __forceinline__ float fast_exp(float x) {
    float t = x * 1.4426950408889634f;
    t = fminf(fmaxf(t, -126.f), 126.f);
    float fi = floorf(t);
    float f  = t - fi;
    int   i  = (int)fi;
    float p = 1.5403530e-4f;
    p = fmaf(p, f, 1.3333558e-3f);
    p = fmaf(p, f, 9.6181291e-3f);
    p = fmaf(p, f, 5.5504109e-2f);
    p = fmaf(p, f, 2.4022651e-1f);
    p = fmaf(p, f, 6.9314718e-1f);
    p = fmaf(p, f, 1.0f);
    return __uint_as_float(__float_as_uint(p) + ((unsigned)i << 23));
}

__device__ __forceinline__ float elu1(float x) {
    return x > 0.f ? x : fast_exp(fmaxf(x, -80.f)) - 1.f;
}

// packed fp32x2 FMA (Blackwell base ISA)
__device__ __forceinline__ unsigned long long rep2(float v) {
    unsigned long long r;
    asm("mov.b64 %0, {%1, %1};" : "=l"(r) : "f"(v));
    return r;
}
__device__ __forceinline__ void ffma2(unsigned long long& d,
                                      unsigned long long a, unsigned long long b) {
    asm("fma.rn.f32x2 %0, %1, %2, %0;" : "+l"(d) : "l"(a), "l"(b));
}
__device__ __forceinline__ float2 unpk(unsigned long long v) {
    float lo, hi;
    asm("mov.b64 {%0, %1}, %2;" : "=f"(lo), "=f"(hi) : "l"(v));
    return make_float2(lo, hi);
}

// ---------------- sort pipeline ----------------
__global__ void zero_cnt_kernel() {
    int i = blockIdx.x * blockDim.x + threadIdx.x;
    if (i < NN) g_cnt[i] = 0;
}

__device__ __forceinline__ bool edge_sd(const int* __restrict__ src,
                                        const int* __restrict__ dst,
                                        int e, int E, int& s, int& d) {
    if (e < E) { s = src[e]; d = dst[e]; }
    else       { s = d = e - E; }
    return (unsigned)s < NN && (unsigned)d < NN;
}

__global__ void hist_kernel(const int* __restrict__ src,
                            const int* __restrict__ dst, int E) {
    int e = blockIdx.x * blockDim.x + threadIdx.x;
    if (e >= E + NN) return;
    int s, d;
    if (!edge_sd(src, dst, e, E, s, d)) return;
    atomicAdd(&g_cnt[d], 1);
}

// inclusive block scan over 1024-elem chunks
__global__ void scan1_kernel() {
    __shared__ int sm[1024];
    int tid = threadIdx.x, i = blockIdx.x * 1024 + tid;
    int v = (i < NN) ? g_cnt[i] : 0;
    sm[tid] = v;
    __syncthreads();
#pragma unroll
    for (int off = 1; off < 1024; off <<= 1) {
        int t = (tid >= off) ? sm[tid - off] : 0;
        __syncthreads();
        sm[tid] += t;
        __syncthreads();
    }
    if (i < NN) g_tmp[i] = sm[tid];
    if (tid == 1023) g_bsum[blockIdx.x] = sm[1023];
}

__global__ void scan2_kernel(int nb) {
    if (threadIdx.x == 0) {
        int run = 0;
        for (int b = 0; b < nb; b++) { int t = g_bsum[b]; g_bsum2[b] = run; run += t; }
    }
}

__global__ void scan3_kernel() {
    int i = blockIdx.x * 1024 + threadIdx.x;
    if (i < NN) {
        int incl = g_tmp[i] + g_bsum2[blockIdx.x];
        g_off[i + 1] = incl;
        g_pos[i]     = incl - g_cnt[i];   // exclusive start
        if (i == 0) g_off[0] = 0;
    }
}

__global__ void scatter_kernel(const int* __restrict__ src,
                               const int* __restrict__ dst, int E) {
    int e = blockIdx.x * blockDim.x + threadIdx.x;
    if (e >= E + NN) return;
    int s, d;
    if (!edge_sd(src, dst, e, E, s, d)) return;
    int p = atomicAdd(&g_pos[d], 1);
    g_esrc[p] = s;
}

// ---------------- compute kernels ----------------
// h1 = x @ W1 (100000x512 @ 512x64), 64x64 tile, 4x4 microtile, packed f32x2
__global__ void gemm1_kernel(const float* __restrict__ x, const float* __restrict__ W) {
    __shared__ __align__(16) float As[32][64];
    __shared__ __align__(16) float Bs[32][64];
    int t  = threadIdx.x;          // 256
    int m0 = blockIdx.x * 64;
    int tx = (t & 15) * 4;
    int ty = (t >> 4) * 4;
    int lm = t & 63;
    int lk = (t >> 6) * 4;
    int kr = t >> 4;
    int nc = (t & 15) * 4;

    unsigned long long acc[4][2];
#pragma unroll
    for (int i = 0; i < 4; i++) { acc[i][0] = 0ull; acc[i][1] = 0ull; }

    int  row = m0 + lm;
    bool rok = row < NN;
    const float4* xrow = (const float4*)(x + (size_t)(rok ? row : 0) * FIN);

    for (int k0 = 0; k0 < FIN; k0 += 32) {
#pragma unroll
        for (int rep = 0; rep < 2; rep++) {
            int kk = lk + rep * 16;
            float4 v = rok ? xrow[(k0 + kk) >> 2] : make_float4(0.f, 0.f, 0.f, 0.f);
            As[kk + 0][lm] = v.x;
            As[kk + 1][lm] = v.y;
            As[kk + 2][lm] = v.z;
            As[kk + 3][lm] = v.w;
        }
#pragma unroll
        for (int rep = 0; rep < 2; rep++) {
            float4 v = *(const float4*)(W + (size_t)(k0 + kr + rep * 16) * D1 + nc);
            *(float4*)&Bs[kr + rep * 16][nc] = v;
        }
        __syncthreads();
#pragma unroll
        for (int kk = 0; kk < 32; kk++) {
            float4 a = *(const float4*)&As[kk][ty];
            ulonglong2 bb = *(const ulonglong2*)&Bs[kk][tx];
            unsigned long long a0 = rep2(a.x), a1 = rep2(a.y),
                               a2 = rep2(a.z), a3 = rep2(a.w);
            ffma2(acc[0][0], a0, bb.x); ffma2(acc[0][1], a0, bb.y);
            ffma2(acc[1][0], a1, bb.x); ffma2(acc[1][1], a1, bb.y);
            ffma2(acc[2][0], a2, bb.x); ffma2(acc[2][1], a2, bb.y);
            ffma2(acc[3][0], a3, bb.x); ffma2(acc[3][1], a3, bb.y);
        }
        __syncthreads();
    }
#pragma unroll
    for (int i = 0; i < 4; i++) {
        int r = m0 + ty + i;
        if (r < NN) {
            float2 u0 = unpk(acc[i][0]), u1 = unpk(acc[i][1]);
            *(float4*)&g_h1[(size_t)r * D1 + tx] = make_float4(u0.x, u0.y, u1.x, u1.y);
        }
    }
}

__global__ void attn1_kernel(const float* __restrict__ a_src, const float* __restrict__ a_dst) {
    int warp = (blockIdx.x * blockDim.x + threadIdx.x) >> 5;
    int lane = threadIdx.x & 31;
    if (warp >= NN) return;
    const float* hrow = g_h1 + (size_t)warp * D1;
    float v0 = hrow[lane], v1 = hrow[lane + 32];
    float s0 = v0 * __ldg(&a_src[lane]),  s1 = v1 * __ldg(&a_src[lane + 32]);
    float d0 = v0 * __ldg(&a_dst[lane]),  d1 = v1 * __ldg(&a_dst[lane + 32]);
#pragma unroll
    for (int off = 4; off; off >>= 1) {
        s0 += __shfl_xor_sync(~0u, s0, off);
        s1 += __shfl_xor_sync(~0u, s1, off);
        d0 += __shfl_xor_sync(~0u, d0, off);
        d1 += __shfl_xor_sync(~0u, d1, off);
    }
    if ((lane & 7) == 0) {
        int h = lane >> 3;
        g_al1[warp * H1 + h]     = s0;
        g_al1[warp * H1 + h + 4] = s1;
        g_ar1[warp * H1 + h]     = d0;
        g_ar1[warp * H1 + h + 4] = d1;
    }
}

// layer-1 aggregation: one warp per dst node, register accumulation, NO atomics.
// lane owns out channels (2*lane, 2*lane+1); their head = lane>>2.
__global__ void agg1_kernel() {
    int d = (blockIdx.x * blockDim.x + threadIdx.x) >> 5;
    int lane = threadIdx.x & 31;
    if (d >= NN) return;
    int beg = g_off[d], end = g_off[d + 1];
    float arh  = (lane < 8) ? g_ar1[d * H1 + lane] : 0.f;
    float dsum = 0.f;
    float accx = 0.f, accy = 0.f;
    for (int b = beg; b < end; b += 32) {
        int n = min(32, end - b);
        int s_my = (b + lane < end) ? g_esrc[b + lane] : 0;
        for (int j = 0; j < n; j++) {
            int s = __shfl_sync(~0u, s_my, j);
            float exh = 0.f;
            if (lane < 8) {
                exh = fast_exp(lrelu(g_al1[s * H1 + lane] + arh));
                dsum += exh;
            }
            float ex = __shfl_sync(~0u, exh, lane >> 2);
            float2 hv = *(const float2*)&g_h1[(size_t)s * D1 + 2 * lane];
            accx = fmaf(hv.x, ex, accx);
            accy = fmaf(hv.y, ex, accy);
        }
    }
    *(float2*)&g_out1[(size_t)d * D1 + 2 * lane] = make_float2(accx, accy);
    if (lane < 8) g_d1[d * H1 + lane] = dsum;
}

// layer-2 node prep: h2 = elu(out1/denom + b1); z2 = h2@W2; attention terms
__global__ void node2_kernel(const float* __restrict__ b1, const float* __restrict__ W2,
                             const float* __restrict__ as2, const float* __restrict__ ad2) {
    int warp = (blockIdx.x * blockDim.x + threadIdx.x) >> 5;
    int lane = threadIdx.x & 31;
    if (warp >= NN) return;
    const float* orow = g_out1 + (size_t)warp * D1;
    float rc0 = 1.f / (g_d1[warp * H1 + (lane >> 3)]     + 1e-16f);
    float rc1 = 1.f / (g_d1[warp * H1 + (lane >> 3) + 4] + 1e-16f);
    float o0 = elu1(fmaf(orow[lane],      rc0, __ldg(&b1[lane])));
    float o1 = elu1(fmaf(orow[lane + 32], rc1, __ldg(&b1[lane + 32])));
    float p[C2];
#pragma unroll
    for (int c = 0; c < C2; c++)
        p[c] = fmaf(o0, __ldg(&W2[lane * C2 + c]),
               o1 * __ldg(&W2[(lane + 32) * C2 + c]));
#pragma unroll
    for (int off = 16; off; off >>= 1)
#pragma unroll
        for (int c = 0; c < C2; c++) p[c] += __shfl_xor_sync(~0u, p[c], off);
    float al = 0.f, ar = 0.f;
#pragma unroll
    for (int c = 0; c < C2; c++) {
        al = fmaf(p[c], __ldg(&as2[c]), al);
        ar = fmaf(p[c], __ldg(&ad2[c]), ar);
    }
    if (lane < C2) g_z2[warp * C2 + lane] = p[lane];
    if (lane == 0) { g_al2[warp] = al; g_ar2[warp] = ar; }
}

// layer-2 aggregation + fused log_softmax: one warp per dst node, no atomics.
__global__ void agg2_kernel(const float* __restrict__ b2, float* __restrict__ out) {
    int d = (blockIdx.x * blockDim.x + threadIdx.x) >> 5;
    int lane = threadIdx.x & 31;
    if (d >= NN) return;
    int beg = g_off[d], end = g_off[d + 1];
    float ard = g_ar2[d];
    float acc = 0.f, dsum = 0.f;
    for (int b = beg; b < end; b += 32) {
        int n = min(32, end - b);
        int s_my = (b + lane < end) ? g_esrc[b + lane] : 0;
        for (int j = 0; j < n; j++) {
            int s = __shfl_sync(~0u, s_my, j);
            float ex = fast_exp(lrelu(g_al2[s] + ard));   // uniform across warp
            if (lane < C2) acc = fmaf(g_z2[s * C2 + lane], ex, acc);
            dsum += ex;   // every lane identical
        }
    }
    float rc = 1.f / (dsum + 1e-16f);
    float v = (lane < C2) ? fmaf(acc, rc, __ldg(&b2[lane])) : -1e30f;
    // log_softmax over 10 lanes (reduce within 16-lane group)
    float m = v;
#pragma unroll
    for (int off = 8; off; off >>= 1)
        m = fmaxf(m, __shfl_xor_sync(~0u, m, off, 16));
    float s = (lane < C2) ? fast_exp(v - m) : 0.f;
#pragma unroll
    for (int off = 8; off; off >>= 1)
        s += __shfl_xor_sync(~0u, s, off, 16);
    float l = m + logf(s);
    if (lane < C2) out[(size_t)d * C2 + lane] = v - l;
}

// ---------------- launch ----------------
extern "C" void kernel_launch(void* const* d_in, const int* in_sizes, int n_in,
                              void* d_out, int out_size) {
    const float* x   = (const float*)d_in[0];
    const int*   ei  = (const int*)d_in[1];    // int32 (JAX x64 disabled)
    const float* W1  = (const float*)d_in[2];
    const float* as1 = (const float*)d_in[3];
    const float* ad1 = (const float*)d_in[4];
    const float* b1  = (const float*)d_in[5];
    const float* W2  = (const float*)d_in[6];
    const float* as2 = (const float*)d_in[7];
    const float* ad2 = (const float*)d_in[8];
    const float* b2  = (const float*)d_in[9];

    int E = in_sizes[1] / 2;
    const int* src = ei;
    const int* dst = ei + E;
    int tot = E + NN;
    int nb1 = (NN + 1023) / 1024;

    // sort edges by dst (reused by both layers)
    zero_cnt_kernel<<<(NN + 255) / 256, 256>>>();
    hist_kernel   <<<(tot + 255) / 256, 256>>>(src, dst, E);
    scan1_kernel  <<<nb1, 1024>>>();
    scan2_kernel  <<<1, 32>>>(nb1);
    scan3_kernel  <<<nb1, 1024>>>();
    scatter_kernel<<<(tot + 255) / 256, 256>>>(src, dst, E);

    gemm1_kernel<<<(NN + 63) / 64, 256>>>(x, W1);
    attn1_kernel<<<(NN * 32 + 255) / 256, 256>>>(as1, ad1);
    agg1_kernel <<<(NN * 32 + 255) / 256, 256>>>();
    node2_kernel<<<(NN * 32 + 255) / 256, 256>>>(b1, W2, as2, ad2);
    agg2_kernel <<<(NN * 32 + 255) / 256, 256>>>(b2, (float*)d_out);
}

// round 6
// speedup vs baseline: 1.4431x; 1.1416x over previous
#include <cuda_runtime.h>
#include <cstdint>

#define NN   100000
#define FIN  512
#define H1   8
#define D1   64      // H1*C1
#define C2   10
#define EMAXSZ 1700000

// ---------------- scratch (no allocs allowed) ----------------
__device__ float g_h1 [NN * D1];     // layer1 features   25.6 MB
__device__ float g_al1[NN * H1];
__device__ float g_ar1[NN * H1];
__device__ float g_d1 [NN * H1];
__device__ float g_out1[NN * D1];
__device__ float g_z2 [NN * C2];
__device__ float g_al2[NN];
__device__ float g_ar2[NN];
// sorted-by-dst edge structures
__device__ int   g_cnt [NN];
__device__ int   g_tmp [NN];
__device__ int   g_bsum[128];
__device__ int   g_bsum2[128];
__device__ int   g_off [NN + 1];
__device__ int   g_pos [NN];
__device__ int   g_esrc[EMAXSZ];

// ---------------- helpers ----------------
__device__ __forceinline__ float lrelu(float x) { return x > 0.f ? x : 0.2f * x; }

__device__ __forceinline__ float fast_exp(float x) {
    float t = x * 1.4426950408889634f;
    t = fminf(fmaxf(t, -126.f), 126.f);
    float fi = floorf(t);
    float f  = t - fi;
    int   i  = (int)fi;
    float p = 1.5403530e-4f;
    p = fmaf(p, f, 1.3333558e-3f);
    p = fmaf(p, f, 9.6181291e-3f);
    p = fmaf(p, f, 5.5504109e-2f);
    p = fmaf(p, f, 2.4022651e-1f);
    p = fmaf(p, f, 6.9314718e-1f);
    p = fmaf(p, f, 1.0f);
    return __uint_as_float(__float_as_uint(p) + ((unsigned)i << 23));
}

__device__ __forceinline__ float elu1(float x) {
    return x > 0.f ? x : fast_exp(fmaxf(x, -80.f)) - 1.f;
}

// packed fp32x2 FMA (Blackwell base ISA)
__device__ __forceinline__ unsigned long long rep2(float v) {
    unsigned long long r;
    asm("mov.b64 %0, {%1, %1};" : "=l"(r) : "f"(v));
    return r;
}
__device__ __forceinline__ void ffma2(unsigned long long& d,
                                      unsigned long long a, unsigned long long b) {
    asm("fma.rn.f32x2 %0, %1, %2, %0;" : "+l"(d) : "l"(a), "l"(b));
}
__device__ __forceinline__ float2 unpk(unsigned long long v) {
    float lo, hi;
    asm("mov.b64 {%0, %1}, %2;" : "=f"(lo), "=f"(hi) : "l"(v));
    return make_float2(lo, hi);
}

// ---------------- sort pipeline ----------------
__global__ void zero_cnt_kernel() {
    int i = blockIdx.x * blockDim.x + threadIdx.x;
    if (i < NN) g_cnt[i] = 0;
}

__device__ __forceinline__ bool edge_sd(const int* __restrict__ src,
                                        const int* __restrict__ dst,
                                        int e, int E, int& s, int& d) {
    if (e < E) { s = src[e]; d = dst[e]; }
    else       { s = d = e - E; }
    return (unsigned)s < NN && (unsigned)d < NN;
}

__global__ void hist_kernel(const int* __restrict__ src,
                            const int* __restrict__ dst, int E) {
    int e = blockIdx.x * blockDim.x + threadIdx.x;
    if (e >= E + NN) return;
    int s, d;
    if (!edge_sd(src, dst, e, E, s, d)) return;
    atomicAdd(&g_cnt[d], 1);
}

__global__ void scan1_kernel() {
    __shared__ int sm[1024];
    int tid = threadIdx.x, i = blockIdx.x * 1024 + tid;
    int v = (i < NN) ? g_cnt[i] : 0;
    sm[tid] = v;
    __syncthreads();
#pragma unroll
    for (int off = 1; off < 1024; off <<= 1) {
        int t = (tid >= off) ? sm[tid - off] : 0;
        __syncthreads();
        sm[tid] += t;
        __syncthreads();
    }
    if (i < NN) g_tmp[i] = sm[tid];
    if (tid == 1023) g_bsum[blockIdx.x] = sm[1023];
}

// parallel scan of block sums (<=128)
__global__ void scan2_kernel(int nb) {
    __shared__ int sm[128];
    int tid = threadIdx.x;
    int v = (tid < nb) ? g_bsum[tid] : 0;
    sm[tid] = v;
    __syncthreads();
#pragma unroll
    for (int off = 1; off < 128; off <<= 1) {
        int t = (tid >= off) ? sm[tid - off] : 0;
        __syncthreads();
        sm[tid] += t;
        __syncthreads();
    }
    if (tid < nb) g_bsum2[tid] = sm[tid] - v;   // exclusive
}

__global__ void scan3_kernel() {
    int i = blockIdx.x * 1024 + threadIdx.x;
    if (i < NN) {
        int incl = g_tmp[i] + g_bsum2[blockIdx.x];
        g_off[i + 1] = incl;
        g_pos[i]     = incl - g_cnt[i];
        if (i == 0) g_off[0] = 0;
    }
}

__global__ void scatter_kernel(const int* __restrict__ src,
                               const int* __restrict__ dst, int E) {
    int e = blockIdx.x * blockDim.x + threadIdx.x;
    if (e >= E + NN) return;
    int s, d;
    if (!edge_sd(src, dst, e, E, s, d)) return;
    int p = atomicAdd(&g_pos[d], 1);
    g_esrc[p] = s;
}

// ---------------- compute kernels ----------------
// h1 = x @ W1 + fused attention-term epilogue
__global__ void gemm1_kernel(const float* __restrict__ x, const float* __restrict__ W,
                             const float* __restrict__ a_src, const float* __restrict__ a_dst) {
    __shared__ __align__(16) float As[32][64];
    __shared__ __align__(16) float Bs[32][64];
    int t  = threadIdx.x;          // 256
    int m0 = blockIdx.x * 64;
    int tx = (t & 15) * 4;
    int ty = (t >> 4) * 4;
    int lm = t & 63;
    int lk = (t >> 6) * 4;
    int kr = t >> 4;
    int nc = (t & 15) * 4;

    unsigned long long acc[4][2];
#pragma unroll
    for (int i = 0; i < 4; i++) { acc[i][0] = 0ull; acc[i][1] = 0ull; }

    int  row = m0 + lm;
    bool rok = row < NN;
    const float4* xrow = (const float4*)(x + (size_t)(rok ? row : 0) * FIN);

    for (int k0 = 0; k0 < FIN; k0 += 32) {
#pragma unroll
        for (int rep = 0; rep < 2; rep++) {
            int kk = lk + rep * 16;
            float4 v = rok ? xrow[(k0 + kk) >> 2] : make_float4(0.f, 0.f, 0.f, 0.f);
            As[kk + 0][lm] = v.x;
            As[kk + 1][lm] = v.y;
            As[kk + 2][lm] = v.z;
            As[kk + 3][lm] = v.w;
        }
#pragma unroll
        for (int rep = 0; rep < 2; rep++) {
            float4 v = *(const float4*)(W + (size_t)(k0 + kr + rep * 16) * D1 + nc);
            *(float4*)&Bs[kr + rep * 16][nc] = v;
        }
        __syncthreads();
#pragma unroll
        for (int kk = 0; kk < 32; kk++) {
            float4 a = *(const float4*)&As[kk][ty];
            ulonglong2 bb = *(const ulonglong2*)&Bs[kk][tx];
            unsigned long long a0 = rep2(a.x), a1 = rep2(a.y),
                               a2 = rep2(a.z), a3 = rep2(a.w);
            ffma2(acc[0][0], a0, bb.x); ffma2(acc[0][1], a0, bb.y);
            ffma2(acc[1][0], a1, bb.x); ffma2(acc[1][1], a1, bb.y);
            ffma2(acc[2][0], a2, bb.x); ffma2(acc[2][1], a2, bb.y);
            ffma2(acc[3][0], a3, bb.x); ffma2(acc[3][1], a3, bb.y);
        }
        __syncthreads();
    }

    float4 as4 = *(const float4*)&a_src[tx];
    float4 ad4 = *(const float4*)&a_dst[tx];
    int h = (t & 15) >> 1;                     // head covered by my 4 columns
#pragma unroll
    for (int i = 0; i < 4; i++) {
        int r = m0 + ty + i;
        float2 u0 = unpk(acc[i][0]), u1 = unpk(acc[i][1]);
        if (r < NN)
            *(float4*)&g_h1[(size_t)r * D1 + tx] = make_float4(u0.x, u0.y, u1.x, u1.y);
        // partial attention dots over my 4 cols; pair-reduce to full head (8 cols)
        float alp = u0.x * as4.x + u0.y * as4.y + u1.x * as4.z + u1.y * as4.w;
        float arp = u0.x * ad4.x + u0.y * ad4.y + u1.x * ad4.z + u1.y * ad4.w;
        alp += __shfl_xor_sync(~0u, alp, 1);
        arp += __shfl_xor_sync(~0u, arp, 1);
        if ((t & 1) == 0 && r < NN) {
            g_al1[r * H1 + h] = alp;
            g_ar1[r * H1 + h] = arp;
        }
    }
}

// layer-1 aggregation: warp per dst node; batch-phase exp computation in smem.
__global__ void agg1_kernel() {
    __shared__ float s_ex[8][256];             // [warpInBlock][edge*8+head]
    int gw = (blockIdx.x * blockDim.x + threadIdx.x) >> 5;
    int w  = (threadIdx.x >> 5);
    int lane = threadIdx.x & 31;
    if (gw >= NN) return;
    int d = gw;
    int beg = g_off[d], end = g_off[d + 1];
    float4 ar0 = *(const float4*)&g_ar1[d * H1];       // uniform broadcast
    float4 ar1 = *(const float4*)&g_ar1[d * H1 + 4];
    float dsum[8];
#pragma unroll
    for (int h = 0; h < 8; h++) dsum[h] = 0.f;
    float accx = 0.f, accy = 0.f;

    for (int b = beg; b < end; b += 32) {
        int n = min(32, end - b);
        int s_my = (lane < n) ? g_esrc[b + lane] : 0;
        // phase 1: lane computes 8 head-exps for its own edge
        float ex[8];
        if (lane < n) {
            float4 a0 = *(const float4*)&g_al1[s_my * H1];
            float4 a1 = *(const float4*)&g_al1[s_my * H1 + 4];
            ex[0] = fast_exp(lrelu(a0.x + ar0.x));
            ex[1] = fast_exp(lrelu(a0.y + ar0.y));
            ex[2] = fast_exp(lrelu(a0.z + ar0.z));
            ex[3] = fast_exp(lrelu(a0.w + ar0.w));
            ex[4] = fast_exp(lrelu(a1.x + ar1.x));
            ex[5] = fast_exp(lrelu(a1.y + ar1.y));
            ex[6] = fast_exp(lrelu(a1.z + ar1.z));
            ex[7] = fast_exp(lrelu(a1.w + ar1.w));
#pragma unroll
            for (int h = 0; h < 8; h++) dsum[h] += ex[h];
            *(float4*)&s_ex[w][lane * 8]     = make_float4(ex[0], ex[1], ex[2], ex[3]);
            *(float4*)&s_ex[w][lane * 8 + 4] = make_float4(ex[4], ex[5], ex[6], ex[7]);
        }
        __syncwarp();
        // phase 2: accumulate h1 rows; lane owns channels (2*lane, 2*lane+1)
        for (int j = 0; j < n; j++) {
            int s = __shfl_sync(~0u, s_my, j);
            float exv = s_ex[w][j * 8 + (lane >> 2)];
            float2 hv = *(const float2*)&g_h1[(size_t)s * D1 + 2 * lane];
            accx = fmaf(hv.x, exv, accx);
            accy = fmaf(hv.y, exv, accy);
        }
        __syncwarp();
    }
    *(float2*)&g_out1[(size_t)d * D1 + 2 * lane] = make_float2(accx, accy);
    // reduce per-head denominators across lanes
#pragma unroll
    for (int h = 0; h < 8; h++) {
#pragma unroll
        for (int off = 16; off; off >>= 1)
            dsum[h] += __shfl_xor_sync(~0u, dsum[h], off);
    }
    if (lane == 0) {
        *(float4*)&g_d1[d * H1]     = make_float4(dsum[0], dsum[1], dsum[2], dsum[3]);
        *(float4*)&g_d1[d * H1 + 4] = make_float4(dsum[4], dsum[5], dsum[6], dsum[7]);
    }
}

// layer-2 node prep
__global__ void node2_kernel(const float* __restrict__ b1, const float* __restrict__ W2,
                             const float* __restrict__ as2, const float* __restrict__ ad2) {
    int warp = (blockIdx.x * blockDim.x + threadIdx.x) >> 5;
    int lane = threadIdx.x & 31;
    if (warp >= NN) return;
    const float* orow = g_out1 + (size_t)warp * D1;
    float rc0 = 1.f / (g_d1[warp * H1 + (lane >> 3)]     + 1e-16f);
    float rc1 = 1.f / (g_d1[warp * H1 + (lane >> 3) + 4] + 1e-16f);
    float o0 = elu1(fmaf(orow[lane],      rc0, __ldg(&b1[lane])));
    float o1 = elu1(fmaf(orow[lane + 32], rc1, __ldg(&b1[lane + 32])));
    float p[C2];
#pragma unroll
    for (int c = 0; c < C2; c++)
        p[c] = fmaf(o0, __ldg(&W2[lane * C2 + c]),
               o1 * __ldg(&W2[(lane + 32) * C2 + c]));
#pragma unroll
    for (int off = 16; off; off >>= 1)
#pragma unroll
        for (int c = 0; c < C2; c++) p[c] += __shfl_xor_sync(~0u, p[c], off);
    float al = 0.f, ar = 0.f;
#pragma unroll
    for (int c = 0; c < C2; c++) {
        al = fmaf(p[c], __ldg(&as2[c]), al);
        ar = fmaf(p[c], __ldg(&ad2[c]), ar);
    }
    if (lane < C2) g_z2[warp * C2 + lane] = p[lane];
    if (lane == 0) { g_al2[warp] = al; g_ar2[warp] = ar; }
}

// layer-2 aggregation + fused log_softmax
__global__ void agg2_kernel(const float* __restrict__ b2, float* __restrict__ out) {
    int d = (blockIdx.x * blockDim.x + threadIdx.x) >> 5;
    int lane = threadIdx.x & 31;
    if (d >= NN) return;
    int beg = g_off[d], end = g_off[d + 1];
    float ard = g_ar2[d];
    float acc = 0.f, dsum = 0.f;
    for (int b = beg; b < end; b += 32) {
        int n = min(32, end - b);
        int s_my = (b + lane < end) ? g_esrc[b + lane] : 0;
        float ex_my = (b + lane < end) ? fast_exp(lrelu(g_al2[s_my] + ard)) : 0.f;
        dsum += ex_my;
        for (int j = 0; j < n; j++) {
            int   s  = __shfl_sync(~0u, s_my, j);
            float ex = __shfl_sync(~0u, ex_my, j);
            if (lane < C2) acc = fmaf(g_z2[s * C2 + lane], ex, acc);
        }
    }
#pragma unroll
    for (int off = 16; off; off >>= 1)
        dsum += __shfl_xor_sync(~0u, dsum, off);
    float rc = 1.f / (dsum + 1e-16f);
    float v = (lane < C2) ? fmaf(acc, rc, __ldg(&b2[lane])) : -1e30f;
    float m = v;
#pragma unroll
    for (int off = 8; off; off >>= 1)
        m = fmaxf(m, __shfl_xor_sync(~0u, m, off, 16));
    float s = (lane < C2) ? fast_exp(v - m) : 0.f;
#pragma unroll
    for (int off = 8; off; off >>= 1)
        s += __shfl_xor_sync(~0u, s, off, 16);
    float l = m + logf(s);
    if (lane < C2) out[(size_t)d * C2 + lane] = v - l;
}

// ---------------- launch ----------------
extern "C" void kernel_launch(void* const* d_in, const int* in_sizes, int n_in,
                              void* d_out, int out_size) {
    const float* x   = (const float*)d_in[0];
    const int*   ei  = (const int*)d_in[1];    // int32 (JAX x64 disabled)
    const float* W1  = (const float*)d_in[2];
    const float* as1 = (const float*)d_in[3];
    const float* ad1 = (const float*)d_in[4];
    const float* b1  = (const float*)d_in[5];
    const float* W2  = (const float*)d_in[6];
    const float* as2 = (const float*)d_in[7];
    const float* ad2 = (const float*)d_in[8];
    const float* b2  = (const float*)d_in[9];

    int E = in_sizes[1] / 2;
    const int* src = ei;
    const int* dst = ei + E;
    int tot = E + NN;
    int nb1 = (NN + 1023) / 1024;

    zero_cnt_kernel<<<(NN + 255) / 256, 256>>>();
    hist_kernel   <<<(tot + 255) / 256, 256>>>(src, dst, E);
    scan1_kernel  <<<nb1, 1024>>>();
    scan2_kernel  <<<1, 128>>>(nb1);
    scan3_kernel  <<<nb1, 1024>>>();
    scatter_kernel<<<(tot + 255) / 256, 256>>>(src, dst, E);

    gemm1_kernel<<<(NN + 63) / 64, 256>>>(x, W1, as1, ad1);
    agg1_kernel <<<(NN * 32 + 255) / 256, 256>>>();
    node2_kernel<<<(NN * 32 + 255) / 256, 256>>>(b1, W2, as2, ad2);
    agg2_kernel <<<(NN * 32 + 255) / 256, 256>>>(b2, (float*)d_out);
}